// round 5
// baseline (speedup 1.0000x reference)
#include <cuda_runtime.h>
#include <cuda_bf16.h>
#include <stdint.h>
#include <math.h>
#include <float.h>

#define DIMM   1024
#define NHEADS 16
#define DH     64
#define SEQ    8192
#define BATCH  2
#define NTOK   (BATCH*SEQ)     // 16384
#define BHTOT  (BATCH*NHEADS)  // 32
#define NWIN   (SEQ/128)       // 64
#define TBLROWS (SEQ + 256)
#define KTOT   3072            // split K' = 3*1024

// ---------------- static device scratch ----------------
__device__ float g_qkv[(size_t)NTOK * 3072];
__device__ float g_q[(size_t)BHTOT * SEQ * DH];
__device__ float g_k[(size_t)BHTOT * SEQ * DH];
__device__ float g_v[(size_t)BHTOT * SEQ * DH];
__device__ float g_attn[(size_t)NTOK * DIMM];
__device__ float g_cos[(size_t)TBLROWS * 32];
__device__ float g_sin[(size_t)TBLROWS * 32];
__device__ __nv_bfloat16 g_a[(size_t)NTOK * KTOT];     // A' split (x, later attn out)
__device__ __nv_bfloat16 g_b1[(size_t)3072 * KTOT];    // w_qkv'^T split
__device__ __nv_bfloat16 g_b2[(size_t)1024 * KTOT];    // w_out'^T split

// ---------------- rope table ----------------
__global__ void rope_table_kernel() {
    int idx = blockIdx.x * 256 + threadIdx.x;
    if (idx >= TBLROWS * 32) return;
    int t = idx >> 5, d = idx & 31;
    float invf = expf(-(float)d * (9.210340371976184f / 32.0f));
    float s, c;
    sincosf((float)t * invf, &s, &c);
    g_cos[idx] = c;
    g_sin[idx] = s;
}

// ---------------- split-bf16 conversions ----------------
// A side: src [NTOK, 1024] f32 -> dst [NTOK, 3072] bf16 chunks (hi, lo, hi)
__global__ void __launch_bounds__(256) convert_a3_kernel(
    const float* __restrict__ src, __nv_bfloat16* __restrict__ dst)
{
    size_t i = (size_t)blockIdx.x * 256 + threadIdx.x;
    int m = (int)(i >> 10), k = (int)(i & 1023);
    float v = src[i];
    __nv_bfloat16 hi = __float2bfloat16(v);
    __nv_bfloat16 lo = __float2bfloat16(v - __bfloat162float(hi));
    __nv_bfloat16* d = dst + (size_t)m * KTOT;
    d[k] = hi; d[1024 + k] = lo; d[2048 + k] = hi;
}

// B side: src [1024, N] f32 row-major -> dst [N, 3072] bf16 (transposed), chunks (hi, hi, lo)
__global__ void __launch_bounds__(1024) convert_b3_kernel(
    const float* __restrict__ src, __nv_bfloat16* __restrict__ dst, int N)
{
    __shared__ float t[32][33];
    int n0 = blockIdx.x * 32, k0 = blockIdx.y * 32;
    int tx = threadIdx.x, ty = threadIdx.y;
    t[ty][tx] = src[(size_t)(k0 + ty) * N + n0 + tx];
    __syncthreads();
    float v = t[tx][ty];   // src[k0+tx][n0+ty]
    __nv_bfloat16 hi = __float2bfloat16(v);
    __nv_bfloat16 lo = __float2bfloat16(v - __bfloat162float(hi));
    size_t base = (size_t)(n0 + ty) * KTOT + k0 + tx;
    dst[base] = hi; dst[base + 1024] = hi; dst[base + 2048] = lo;
}

// ---------------- HMMA bf16 GEMM: C[M,Ntot] = A'[M,3072] @ B'[Ntot,3072]^T ----
// BM=128, BN=128, BK=32, 256 threads, 8 warps (2 M x 4 N), warp tile 64x32.
// 3-stage cp.async pipeline. Fragments via mma.sync.m16n8k16 (row.col).
#define GEMM_NIT   (KTOT / 32)   // 96
#define ROWU       20            // u32 per smem row (16 data + 4 pad, 16B aligned)
#define STAGEU     (2 * 128 * ROWU)   // A + B per stage in u32
#define GEMM_SMEM  (3 * STAGEU * 4)   // 61440 bytes

__device__ __forceinline__ uint32_t smem_u32g(const void* p) {
    uint32_t a;
    asm("{ .reg .u64 t; cvta.to.shared.u64 t, %1; cvt.u32.u64 %0, t; }" : "=r"(a) : "l"(p));
    return a;
}

__device__ __forceinline__ void hmma16816(float c[4], uint32_t a0, uint32_t a1,
                                          uint32_t a2, uint32_t a3,
                                          uint32_t b0, uint32_t b1) {
    asm volatile(
        "mma.sync.aligned.m16n8k16.row.col.f32.bf16.bf16.f32 "
        "{%0,%1,%2,%3}, {%4,%5,%6,%7}, {%8,%9}, {%0,%1,%2,%3};\n"
        : "+f"(c[0]), "+f"(c[1]), "+f"(c[2]), "+f"(c[3])
        : "r"(a0), "r"(a1), "r"(a2), "r"(a3), "r"(b0), "r"(b1));
}

__global__ void __launch_bounds__(256, 2) gemm3x_kernel(
    const __nv_bfloat16* __restrict__ A, const __nv_bfloat16* __restrict__ Bm,
    float* __restrict__ C, int Ntot)
{
    extern __shared__ uint32_t smem[];
    int tid = threadIdx.x;
    int wid = tid >> 5, lane = tid & 31;
    int wm = wid >> 2, wn = wid & 3;       // warp grid 2 x 4
    int g = lane >> 2, tig = lane & 3;
    int brow = blockIdx.y, bcol = blockIdx.x;

    const __nv_bfloat16* Ag = A + (size_t)(brow * 128) * KTOT;
    const __nv_bfloat16* Bg = Bm + (size_t)(bcol * 128) * KTOT;

    uint32_t smb = smem_u32g(smem);

    // cp.async: 512 16B-chunks per tile; thread t does chunks t, t+256.
    int ch0 = tid, ch1 = tid + 256;
    int r0c = ch0 >> 2, c40 = ch0 & 3;     // row, 16B-group
    int r1c = ch1 >> 2, c41 = ch1 & 3;

#define LOAD_STAGE(kc, stg) do { \
    uint32_t ab = smb + (stg) * STAGEU * 4; \
    uint32_t bb = ab + 128 * ROWU * 4; \
    const __nv_bfloat16* gA0 = Ag + (size_t)r0c * KTOT + (kc) * 32 + c40 * 8; \
    const __nv_bfloat16* gA1 = Ag + (size_t)r1c * KTOT + (kc) * 32 + c41 * 8; \
    const __nv_bfloat16* gB0 = Bg + (size_t)r0c * KTOT + (kc) * 32 + c40 * 8; \
    const __nv_bfloat16* gB1 = Bg + (size_t)r1c * KTOT + (kc) * 32 + c41 * 8; \
    asm volatile("cp.async.cg.shared.global [%0], [%1], 16;" :: "r"(ab + (r0c * ROWU + c40 * 4) * 4), "l"(gA0)); \
    asm volatile("cp.async.cg.shared.global [%0], [%1], 16;" :: "r"(ab + (r1c * ROWU + c41 * 4) * 4), "l"(gA1)); \
    asm volatile("cp.async.cg.shared.global [%0], [%1], 16;" :: "r"(bb + (r0c * ROWU + c40 * 4) * 4), "l"(gB0)); \
    asm volatile("cp.async.cg.shared.global [%0], [%1], 16;" :: "r"(bb + (r1c * ROWU + c41 * 4) * 4), "l"(gB1)); \
} while (0)

    LOAD_STAGE(0, 0);
    asm volatile("cp.async.commit_group;" ::: "memory");
    LOAD_STAGE(1, 1);
    asm volatile("cp.async.commit_group;" ::: "memory");
    LOAD_STAGE(2, 2);
    asm volatile("cp.async.commit_group;" ::: "memory");

    float acc[4][4][4];
    #pragma unroll
    for (int mt = 0; mt < 4; mt++)
        #pragma unroll
        for (int nt = 0; nt < 4; nt++)
            #pragma unroll
            for (int e = 0; e < 4; e++) acc[mt][nt][e] = 0.0f;

    for (int kc = 0; kc < GEMM_NIT; kc++) {
        int stg = kc % 3;
        asm volatile("cp.async.wait_group 2;" ::: "memory");
        __syncthreads();

        const uint32_t* As = smem + stg * STAGEU;
        const uint32_t* Bs = As + 128 * ROWU;

        #pragma unroll
        for (int ks = 0; ks < 2; ks++) {
            uint32_t af[4][4], bf[4][2];
            #pragma unroll
            for (int mt = 0; mt < 4; mt++) {
                int r = wm * 64 + mt * 16 + g;
                af[mt][0] = As[r * ROWU + ks * 8 + tig];
                af[mt][1] = As[(r + 8) * ROWU + ks * 8 + tig];
                af[mt][2] = As[r * ROWU + ks * 8 + tig + 4];
                af[mt][3] = As[(r + 8) * ROWU + ks * 8 + tig + 4];
            }
            #pragma unroll
            for (int nt = 0; nt < 4; nt++) {
                int n = wn * 32 + nt * 8 + g;
                bf[nt][0] = Bs[n * ROWU + ks * 8 + tig];
                bf[nt][1] = Bs[n * ROWU + ks * 8 + tig + 4];
            }
            #pragma unroll
            for (int mt = 0; mt < 4; mt++)
                #pragma unroll
                for (int nt = 0; nt < 4; nt++)
                    hmma16816(acc[mt][nt], af[mt][0], af[mt][1], af[mt][2], af[mt][3],
                              bf[nt][0], bf[nt][1]);
        }
        __syncthreads();
        if (kc + 3 < GEMM_NIT) LOAD_STAGE(kc + 3, stg);
        asm volatile("cp.async.commit_group;" ::: "memory");   // empty group when no load
    }

    // epilogue
    #pragma unroll
    for (int mt = 0; mt < 4; mt++) {
        int row = brow * 128 + wm * 64 + mt * 16 + g;
        #pragma unroll
        for (int nt = 0; nt < 4; nt++) {
            int col = bcol * 128 + wn * 32 + nt * 8 + tig * 2;
            *(float2*)(C + (size_t)row * Ntot + col) =
                make_float2(acc[mt][nt][0], acc[mt][nt][1]);
            *(float2*)(C + (size_t)(row + 8) * Ntot + col) =
                make_float2(acc[mt][nt][2], acc[mt][nt][3]);
        }
    }
#undef LOAD_STAGE
}

// ---------------- normalize + scale + RoPE + split ----------------
__global__ void __launch_bounds__(256) norm_rope_split_kernel(
    const float* __restrict__ qkv,
    const float* __restrict__ q_scale,
    const float* __restrict__ k_scale)
{
    int r = blockIdx.x * blockDim.y + threadIdx.y;
    int lane = threadIdx.x;
    int m = r >> 4;
    int h = r & 15;
    int b = m >> 13;
    int nn = m & (SEQ - 1);
    int bh = b * NHEADS + h;

    const float* row = qkv + (size_t)m * 3072 + h * 64;
    float q1 = row[lane],        q2 = row[lane + 32];
    float k1 = row[1024 + lane], k2 = row[1024 + lane + 32];
    float v1 = row[2048 + lane], v2 = row[2048 + lane + 32];

    float qs = q1 * q1 + q2 * q2;
    float ks = k1 * k1 + k2 * k2;
    #pragma unroll
    for (int o = 16; o > 0; o >>= 1) {
        qs += __shfl_xor_sync(0xffffffffu, qs, o);
        ks += __shfl_xor_sync(0xffffffffu, ks, o);
    }
    float qinv = 8.0f / fmaxf(sqrtf(qs), 1e-12f);
    float kinv = 1.0f / fmaxf(sqrtf(ks), 1e-12f);

    q1 = q1 * qinv * q_scale[lane];  q2 = q2 * qinv * q_scale[lane + 32];
    k1 = k1 * kinv * k_scale[lane];  k2 = k2 * kinv * k_scale[lane + 32];

    int tq = nn + 128, tk = nn;
    float cq = g_cos[tq * 32 + lane], sq = g_sin[tq * 32 + lane];
    float ck = g_cos[tk * 32 + lane], sk = g_sin[tk * 32 + lane];
    float qo1 = q1 * cq - q2 * sq, qo2 = q2 * cq + q1 * sq;
    float ko1 = k1 * ck - k2 * sk, ko2 = k2 * ck + k1 * sk;

    size_t base = ((size_t)bh * SEQ + nn) * 64;
    g_q[base + lane] = qo1;  g_q[base + lane + 32] = qo2;
    g_k[base + lane] = ko1;  g_k[base + lane + 32] = ko2;
    g_v[base + lane] = v1;   g_v[base + lane + 32] = v2;
}

// ---------------- windowed attention ----------------
#define ATTN_SMEM_FLOATS (64*128 + 64*128 + 128*64 + 128*136)

__global__ void __launch_bounds__(256) local_attn_kernel() {
    int w  = blockIdx.x;
    int bh = blockIdx.y;
    extern __shared__ float smf[];
    float* qT = smf;
    float* kT = qT + 64 * 128;
    float* vS = kT + 64 * 128;
    float* Pt = vS + 128 * 64;

    int tid = threadIdx.x;
    int tx = tid & 15, ty = tid >> 4;

    const float* qg = g_q + ((size_t)bh * SEQ + (size_t)w * 128) * 64;

    #pragma unroll
    for (int it = 0; it < 8; it++) {
        int f = tid + it * 256;
        int i = f & 127, d4 = (f >> 7) * 4;
        float4 v = *(const float4*)(qg + (size_t)i * 64 + d4);
        qT[(d4 + 0) * 128 + i] = v.x;
        qT[(d4 + 1) * 128 + i] = v.y;
        qT[(d4 + 2) * 128 + i] = v.z;
        qT[(d4 + 3) * 128 + i] = v.w;
    }

    float O[8][4];
    float mrow[8], lrow[8];
    #pragma unroll
    for (int r = 0; r < 8; r++) {
        mrow[r] = -FLT_MAX; lrow[r] = 0.0f;
        #pragma unroll
        for (int c = 0; c < 4; c++) O[r][c] = 0.0f;
    }

    for (int ch = 0; ch < 3; ch++) {
        int kw = w - 1 + ch;
        if (kw < 0 || kw >= NWIN) continue;
        const float* kg = g_k + ((size_t)bh * SEQ + (size_t)kw * 128) * 64;
        const float* vg = g_v + ((size_t)bh * SEQ + (size_t)kw * 128) * 64;

        __syncthreads();
        #pragma unroll
        for (int it = 0; it < 8; it++) {
            int f = tid + it * 256;
            int i = f & 127, d4 = (f >> 7) * 4;
            float4 v = *(const float4*)(kg + (size_t)i * 64 + d4);
            kT[(d4 + 0) * 128 + i] = v.x;
            kT[(d4 + 1) * 128 + i] = v.y;
            kT[(d4 + 2) * 128 + i] = v.z;
            kT[(d4 + 3) * 128 + i] = v.w;
        }
        #pragma unroll
        for (int it = 0; it < 8; it++) {
            int f = tid + it * 256;
            int j = f >> 4, d4 = (f & 15) * 4;
            *(float4*)(vS + j * 64 + d4) = *(const float4*)(vg + (size_t)j * 64 + d4);
        }
        __syncthreads();

        float S[8][8];
        #pragma unroll
        for (int r = 0; r < 8; r++)
            #pragma unroll
            for (int c = 0; c < 8; c++) S[r][c] = 0.0f;

        #pragma unroll 16
        for (int d = 0; d < 64; d++) {
            float a[8], bb[8];
            *(float4*)&a[0]  = *(const float4*)(qT + d * 128 + ty * 8);
            *(float4*)&a[4]  = *(const float4*)(qT + d * 128 + ty * 8 + 4);
            *(float4*)&bb[0] = *(const float4*)(kT + d * 128 + tx * 8);
            *(float4*)&bb[4] = *(const float4*)(kT + d * 128 + tx * 8 + 4);
            #pragma unroll
            for (int r = 0; r < 8; r++)
                #pragma unroll
                for (int c = 0; c < 8; c++)
                    S[r][c] += a[r] * bb[c];
        }

        if (ch == 0) {
            #pragma unroll
            for (int r = 0; r < 8; r++)
                #pragma unroll
                for (int c = 0; c < 8; c++)
                    if (tx * 8 + c < ty * 8 + r) S[r][c] = -FLT_MAX;
        } else if (ch == 2) {
            #pragma unroll
            for (int r = 0; r < 8; r++)
                #pragma unroll
                for (int c = 0; c < 8; c++)
                    if (tx * 8 + c > ty * 8 + r) S[r][c] = -FLT_MAX;
        }

        #pragma unroll
        for (int r = 0; r < 8; r++) {
            float rm = S[r][0];
            #pragma unroll
            for (int c = 1; c < 8; c++) rm = fmaxf(rm, S[r][c]);
            #pragma unroll
            for (int o = 1; o < 16; o <<= 1)
                rm = fmaxf(rm, __shfl_xor_sync(0xffffffffu, rm, o));
            float mn = fmaxf(mrow[r], rm);
            float alpha = expf(mrow[r] - mn);
            float rs = 0.0f;
            #pragma unroll
            for (int c = 0; c < 8; c++) {
                float p = expf(S[r][c] - mn);
                S[r][c] = p;
                rs += p;
            }
            #pragma unroll
            for (int o = 1; o < 16; o <<= 1)
                rs += __shfl_xor_sync(0xffffffffu, rs, o);
            lrow[r] = lrow[r] * alpha + rs;
            mrow[r] = mn;
            #pragma unroll
            for (int c = 0; c < 4; c++) O[r][c] *= alpha;
        }

        #pragma unroll
        for (int r = 0; r < 8; r++) {
            float* pr = Pt + (ty * 8 + r) * 136 + tx * 8;
            *(float4*)(pr)     = make_float4(S[r][0], S[r][1], S[r][2], S[r][3]);
            *(float4*)(pr + 4) = make_float4(S[r][4], S[r][5], S[r][6], S[r][7]);
        }
        __syncthreads();

        #pragma unroll 4
        for (int j0 = 0; j0 < 128; j0 += 4) {
            float4 b0 = *(const float4*)(vS + (j0 + 0) * 64 + tx * 4);
            float4 b1 = *(const float4*)(vS + (j0 + 1) * 64 + tx * 4);
            float4 b2 = *(const float4*)(vS + (j0 + 2) * 64 + tx * 4);
            float4 b3 = *(const float4*)(vS + (j0 + 3) * 64 + tx * 4);
            #pragma unroll
            for (int r = 0; r < 8; r++) {
                float4 a = *(const float4*)(Pt + (ty * 8 + r) * 136 + j0);
                O[r][0] += a.x * b0.x + a.y * b1.x + a.z * b2.x + a.w * b3.x;
                O[r][1] += a.x * b0.y + a.y * b1.y + a.z * b2.y + a.w * b3.y;
                O[r][2] += a.x * b0.z + a.y * b1.z + a.z * b2.z + a.w * b3.z;
                O[r][3] += a.x * b0.w + a.y * b1.w + a.z * b2.w + a.w * b3.w;
            }
        }
    }

    int b = bh >> 4, h = bh & 15;
    size_t out_base = ((size_t)(b * SEQ + w * 128)) * DIMM + h * 64;
    #pragma unroll
    for (int r = 0; r < 8; r++) {
        float inv = 1.0f / lrow[r];
        int i = ty * 8 + r;
        *(float4*)(g_attn + out_base + (size_t)i * DIMM + tx * 4) =
            make_float4(O[r][0] * inv, O[r][1] * inv, O[r][2] * inv, O[r][3] * inv);
    }
}

// ---------------- launch ----------------
extern "C" void kernel_launch(void* const* d_in, const int* in_sizes, int n_in,
                              void* d_out, int out_size) {
    const float* x       = (const float*)d_in[0];
    const float* w_qkv   = (const float*)d_in[1];
    const float* w_out   = (const float*)d_in[2];
    const float* q_scale = (const float*)d_in[3];
    const float* k_scale = (const float*)d_in[4];
    float* out = (float*)d_out;

    void *p_qkv, *p_attn, *p_a, *p_b1, *p_b2;
    cudaGetSymbolAddress(&p_qkv, g_qkv);
    cudaGetSymbolAddress(&p_attn, g_attn);
    cudaGetSymbolAddress(&p_a, g_a);
    cudaGetSymbolAddress(&p_b1, g_b1);
    cudaGetSymbolAddress(&p_b2, g_b2);

    int attn_smem = ATTN_SMEM_FLOATS * (int)sizeof(float);
    cudaFuncSetAttribute(local_attn_kernel,
                         cudaFuncAttributeMaxDynamicSharedMemorySize, attn_smem);
    cudaFuncSetAttribute(gemm3x_kernel,
                         cudaFuncAttributeMaxDynamicSharedMemorySize, GEMM_SMEM);

    // 1) rope tables
    rope_table_kernel<<<(TBLROWS * 32 + 255) / 256, 256>>>();

    // 2) split-bf16 conversions
    convert_a3_kernel<<<(NTOK * 1024) / 256, 256>>>(x, (__nv_bfloat16*)p_a);
    convert_b3_kernel<<<dim3(3072 / 32, 1024 / 32), dim3(32, 32)>>>(
        w_qkv, (__nv_bfloat16*)p_b1, 3072);
    convert_b3_kernel<<<dim3(1024 / 32, 1024 / 32), dim3(32, 32)>>>(
        w_out, (__nv_bfloat16*)p_b2, 1024);

    // 3) QKV projection (HMMA): [16384,3072] = A' @ B1'^T
    gemm3x_kernel<<<dim3(3072 / 128, NTOK / 128), 256, GEMM_SMEM>>>(
        (const __nv_bfloat16*)p_a, (const __nv_bfloat16*)p_b1, (float*)p_qkv, 3072);

    // 4) l2norm + scale + rope + split
    norm_rope_split_kernel<<<(NTOK * NHEADS) / 8, dim3(32, 8)>>>(
        (const float*)p_qkv, q_scale, k_scale);

    // 5) windowed attention
    local_attn_kernel<<<dim3(NWIN, BHTOT), 256, attn_smem>>>();

    // 6) convert attention output, then output projection
    convert_a3_kernel<<<(NTOK * 1024) / 256, 256>>>(
        (const float*)p_attn, (__nv_bfloat16*)p_a);
    gemm3x_kernel<<<dim3(1024 / 128, NTOK / 128), 256, GEMM_SMEM>>>(
        (const __nv_bfloat16*)p_a, (const __nv_bfloat16*)p_b2, out, 1024);
}

// round 6
// speedup vs baseline: 1.7209x; 1.7209x over previous
#include <cuda_runtime.h>
#include <cuda_bf16.h>
#include <stdint.h>
#include <math.h>
#include <float.h>

#define DIMM   1024
#define NHEADS 16
#define SEQ    8192
#define NTOK   16384
#define BHTOT  32
#define NWIN   64
#define TBLROWS (SEQ + 256)
#define KTOT   3072

__device__ float g_qkv[(size_t)NTOK * 3072];
__device__ float g_v[(size_t)BHTOT * SEQ * 64];
__device__ float g_cos[(size_t)TBLROWS * 32];
__device__ float g_sin[(size_t)TBLROWS * 32];
__device__ __nv_bfloat16 g_a[(size_t)NTOK * KTOT];
__device__ __nv_bfloat16 g_b1[(size_t)3072 * KTOT];
__device__ __nv_bfloat16 g_b2[(size_t)1024 * KTOT];
__device__ __nv_bfloat16 g_qh[(size_t)BHTOT * SEQ * 64];
__device__ __nv_bfloat16 g_ql[(size_t)BHTOT * SEQ * 64];
__device__ __nv_bfloat16 g_kh[(size_t)BHTOT * SEQ * 64];
__device__ __nv_bfloat16 g_kl[(size_t)BHTOT * SEQ * 64];

__device__ __forceinline__ uint32_t smem_u32g(const void* p) {
    uint32_t a;
    asm("{ .reg .u64 t; cvta.to.shared.u64 t, %1; cvt.u32.u64 %0, t; }" : "=r"(a) : "l"(p));
    return a;
}
__device__ __forceinline__ void hmma16816(float c[4], uint32_t a0, uint32_t a1,
                                          uint32_t a2, uint32_t a3,
                                          uint32_t b0, uint32_t b1) {
    asm volatile("mma.sync.aligned.m16n8k16.row.col.f32.bf16.bf16.f32 "
        "{%0,%1,%2,%3}, {%4,%5,%6,%7}, {%8,%9}, {%0,%1,%2,%3};\n"
        : "+f"(c[0]), "+f"(c[1]), "+f"(c[2]), "+f"(c[3])
        : "r"(a0), "r"(a1), "r"(a2), "r"(a3), "r"(b0), "r"(b1));
}
#define LDMX4(r0,r1,r2,r3,addr) \
    asm volatile("ldmatrix.sync.aligned.m8n8.x4.shared.b16 {%0,%1,%2,%3}, [%4];" \
        : "=r"(r0),"=r"(r1),"=r"(r2),"=r"(r3) : "r"(addr))

__device__ __forceinline__ float fexp(float x) {
    x = fmaxf(x, -80.0f);
    float t = fmaf(x, 1.4426950408889634f, 12582912.0f);
    float i = t - 12582912.0f;
    float f = fmaf(x, 1.4426950408889634f, -i);
    float p =          1.3333558146e-3f;
    p = fmaf(p, f,     9.6181291057e-3f);
    p = fmaf(p, f,     5.5504108664e-2f);
    p = fmaf(p, f,     2.4022650695e-1f);
    p = fmaf(p, f,     6.9314718056e-1f);
    p = fmaf(p, f,     1.0f);
    return __int_as_float(__float_as_int(p) + (((int)i) << 23));
}
__device__ __forceinline__ uint32_t pack_bf(float a, float b) {
    __nv_bfloat16 x = __float2bfloat16(a), y = __float2bfloat16(b);
    return (uint32_t)__bfloat16_as_ushort(x) | ((uint32_t)__bfloat16_as_ushort(y) << 16);
}

__global__ void rope_table_kernel() {
    int idx = blockIdx.x * 256 + threadIdx.x;
    if (idx >= TBLROWS * 32) return;
    int t = idx >> 5, d = idx & 31;
    float invf = expf(-(float)d * (9.210340371976184f / 32.0f));
    float s, c;
    sincosf((float)t * invf, &s, &c);
    g_cos[idx] = c; g_sin[idx] = s;
}

__global__ void __launch_bounds__(256) convert_a3_kernel(
    const float* __restrict__ src, __nv_bfloat16* __restrict__ dst)
{
    size_t i = (size_t)blockIdx.x * 256 + threadIdx.x;
    int m = (int)(i >> 10), k = (int)(i & 1023);
    float v = src[i];
    __nv_bfloat16 hi = __float2bfloat16(v);
    __nv_bfloat16 lo = __float2bfloat16(v - __bfloat162float(hi));
    __nv_bfloat16* d = dst + (size_t)m * KTOT;
    d[k] = hi; d[1024 + k] = lo; d[2048 + k] = hi;
}

__global__ void __launch_bounds__(1024) convert_b3_kernel(
    const float* __restrict__ src, __nv_bfloat16* __restrict__ dst, int N)
{
    __shared__ float t[32][33];
    int n0 = blockIdx.x * 32, k0 = blockIdx.y * 32;
    int tx = threadIdx.x, ty = threadIdx.y;
    t[ty][tx] = src[(size_t)(k0 + ty) * N + n0 + tx];
    __syncthreads();
    float v = t[tx][ty];
    __nv_bfloat16 hi = __float2bfloat16(v);
    __nv_bfloat16 lo = __float2bfloat16(v - __bfloat162float(hi));
    size_t base = (size_t)(n0 + ty) * KTOT + k0 + tx;
    dst[base] = hi; dst[base + 1024] = hi; dst[base + 2048] = lo;
}

// ---------------- HMMA GEMM, ldmatrix fragments ----------------
#define GEMM_NIT   (KTOT / 32)
#define ROWU       20
#define STAGEU     (2 * 128 * ROWU)
#define GEMM_SMEM  (3 * STAGEU * 4)

__global__ void __launch_bounds__(256, 2) gemm3x_kernel(
    const __nv_bfloat16* __restrict__ A, const __nv_bfloat16* __restrict__ Bm,
    float* __restrict__ C, int Ntot)
{
    extern __shared__ uint32_t smem[];
    int tid = threadIdx.x;
    int wid = tid >> 5, lane = tid & 31;
    int wm = wid >> 2, wn = wid & 3;
    int g = lane >> 2, tig = lane & 3;
    int lr = lane & 15, lh = lane >> 4;
    int brow = blockIdx.y, bcol = blockIdx.x;

    const __nv_bfloat16* Ag = A + (size_t)(brow * 128) * KTOT;
    const __nv_bfloat16* Bg = Bm + (size_t)(bcol * 128) * KTOT;
    uint32_t smb = smem_u32g(smem);

    int r0c = tid >> 2, c40 = tid & 3;
    int r1c = (tid + 256) >> 2, c41 = tid & 3;

#define LOAD_STAGE(kc, stg) do { \
    uint32_t ab = smb + (stg) * STAGEU * 4; \
    uint32_t bb = ab + 128 * ROWU * 4; \
    const __nv_bfloat16* gA0 = Ag + (size_t)r0c * KTOT + (kc) * 32 + c40 * 8; \
    const __nv_bfloat16* gA1 = Ag + (size_t)r1c * KTOT + (kc) * 32 + c41 * 8; \
    const __nv_bfloat16* gB0 = Bg + (size_t)r0c * KTOT + (kc) * 32 + c40 * 8; \
    const __nv_bfloat16* gB1 = Bg + (size_t)r1c * KTOT + (kc) * 32 + c41 * 8; \
    asm volatile("cp.async.cg.shared.global [%0], [%1], 16;" :: "r"(ab + (r0c * ROWU + c40 * 4) * 4), "l"(gA0)); \
    asm volatile("cp.async.cg.shared.global [%0], [%1], 16;" :: "r"(ab + (r1c * ROWU + c41 * 4) * 4), "l"(gA1)); \
    asm volatile("cp.async.cg.shared.global [%0], [%1], 16;" :: "r"(bb + (r0c * ROWU + c40 * 4) * 4), "l"(gB0)); \
    asm volatile("cp.async.cg.shared.global [%0], [%1], 16;" :: "r"(bb + (r1c * ROWU + c41 * 4) * 4), "l"(gB1)); \
} while (0)

    LOAD_STAGE(0, 0);
    asm volatile("cp.async.commit_group;" ::: "memory");
    LOAD_STAGE(1, 1);
    asm volatile("cp.async.commit_group;" ::: "memory");
    LOAD_STAGE(2, 2);
    asm volatile("cp.async.commit_group;" ::: "memory");

    float acc[4][4][4];
    #pragma unroll
    for (int mt = 0; mt < 4; mt++)
        #pragma unroll
        for (int nt = 0; nt < 4; nt++)
            #pragma unroll
            for (int e = 0; e < 4; e++) acc[mt][nt][e] = 0.0f;

    for (int kc = 0; kc < GEMM_NIT; kc++) {
        int stg = kc % 3;
        asm volatile("cp.async.wait_group 2;" ::: "memory");
        __syncthreads();
        uint32_t as_u = smb + stg * STAGEU * 4;
        uint32_t bs_u = as_u + 128 * ROWU * 4;

        #pragma unroll
        for (int ks = 0; ks < 2; ks++) {
            uint32_t af[4][4], bt[4][2];
            #pragma unroll
            for (int mt = 0; mt < 4; mt++) {
                uint32_t addr = as_u + (uint32_t)((wm * 64 + mt * 16 + lr) * ROWU * 4 + ks * 32 + lh * 16);
                LDMX4(af[mt][0], af[mt][1], af[mt][2], af[mt][3], addr);
            }
            #pragma unroll
            for (int bp = 0; bp < 2; bp++) {
                uint32_t t0, t1, t2, t3;
                uint32_t addr = bs_u + (uint32_t)((wn * 32 + bp * 16 + lr) * ROWU * 4 + ks * 32 + lh * 16);
                LDMX4(t0, t1, t2, t3, addr);
                bt[2*bp][0] = t0; bt[2*bp][1] = t2;
                bt[2*bp+1][0] = t1; bt[2*bp+1][1] = t3;
            }
            #pragma unroll
            for (int mt = 0; mt < 4; mt++)
                #pragma unroll
                for (int nt = 0; nt < 4; nt++)
                    hmma16816(acc[mt][nt], af[mt][0], af[mt][1], af[mt][2], af[mt][3],
                              bt[nt][0], bt[nt][1]);
        }
        __syncthreads();
        if (kc + 3 < GEMM_NIT) LOAD_STAGE(kc + 3, stg);
        asm volatile("cp.async.commit_group;" ::: "memory");
    }

    #pragma unroll
    for (int mt = 0; mt < 4; mt++) {
        int row = brow * 128 + wm * 64 + mt * 16 + g;
        #pragma unroll
        for (int nt = 0; nt < 4; nt++) {
            int col = bcol * 128 + wn * 32 + nt * 8 + tig * 2;
            *(float2*)(C + (size_t)row * Ntot + col) = make_float2(acc[mt][nt][0], acc[mt][nt][1]);
            *(float2*)(C + (size_t)(row + 8) * Ntot + col) = make_float2(acc[mt][nt][2], acc[mt][nt][3]);
        }
    }
#undef LOAD_STAGE
}

// ---------------- norm + rope + split (bf16 hi/lo q,k; f32 v) ----------------
__global__ void __launch_bounds__(256) norm_rope_split_kernel(
    const float* __restrict__ qkv,
    const float* __restrict__ q_scale,
    const float* __restrict__ k_scale)
{
    int r = blockIdx.x * blockDim.y + threadIdx.y;
    int lane = threadIdx.x;
    int m = r >> 4, h = r & 15;
    int b = m >> 13, nn = m & (SEQ - 1);
    int bh = b * NHEADS + h;

    const float* row = qkv + (size_t)m * 3072 + h * 64;
    float q1 = row[lane],        q2 = row[lane + 32];
    float k1 = row[1024 + lane], k2 = row[1024 + lane + 32];
    float v1 = row[2048 + lane], v2 = row[2048 + lane + 32];

    float qs = q1 * q1 + q2 * q2, ks = k1 * k1 + k2 * k2;
    #pragma unroll
    for (int o = 16; o > 0; o >>= 1) {
        qs += __shfl_xor_sync(0xffffffffu, qs, o);
        ks += __shfl_xor_sync(0xffffffffu, ks, o);
    }
    float qinv = 8.0f / fmaxf(sqrtf(qs), 1e-12f);
    float kinv = 1.0f / fmaxf(sqrtf(ks), 1e-12f);
    q1 = q1 * qinv * q_scale[lane];  q2 = q2 * qinv * q_scale[lane + 32];
    k1 = k1 * kinv * k_scale[lane];  k2 = k2 * kinv * k_scale[lane + 32];

    int tq = nn + 128, tk = nn;
    float cq = g_cos[tq * 32 + lane], sq = g_sin[tq * 32 + lane];
    float ck = g_cos[tk * 32 + lane], sk = g_sin[tk * 32 + lane];
    float qo1 = q1 * cq - q2 * sq, qo2 = q2 * cq + q1 * sq;
    float ko1 = k1 * ck - k2 * sk, ko2 = k2 * ck + k1 * sk;

    size_t base = ((size_t)bh * SEQ + nn) * 64;
    __nv_bfloat16 t;
    t = __float2bfloat16(qo1); g_qh[base+lane]    = t; g_ql[base+lane]    = __float2bfloat16(qo1 - __bfloat162float(t));
    t = __float2bfloat16(qo2); g_qh[base+lane+32] = t; g_ql[base+lane+32] = __float2bfloat16(qo2 - __bfloat162float(t));
    t = __float2bfloat16(ko1); g_kh[base+lane]    = t; g_kl[base+lane]    = __float2bfloat16(ko1 - __bfloat162float(t));
    t = __float2bfloat16(ko2); g_kh[base+lane+32] = t; g_kl[base+lane+32] = __float2bfloat16(ko2 - __bfloat162float(t));
    g_v[base + lane] = v1; g_v[base + lane + 32] = v2;
}

// ---------------- windowed attention, HMMA split-bf16 flash ----------------
#define AQH 0u
#define AQL 18432u
#define AKH 36864u
#define AKL 55296u
#define AVH 73728u
#define AVL 91136u
#define ATTN_SMEM 108544

__global__ void __launch_bounds__(256) local_attn_kernel() {
    int w = blockIdx.x, bh = blockIdx.y;
    extern __shared__ __align__(16) unsigned char sm[];
    uint32_t smb = smem_u32g(sm);
    int tid = threadIdx.x, wid = tid >> 5, lane = tid & 31;
    int g = lane >> 2, tg = lane & 3, lr = lane & 15, lh = lane >> 4;

    size_t qoff = ((size_t)bh * SEQ + (size_t)w * 128) * 64;
    #pragma unroll
    for (int it = 0; it < 4; it++) {
        int c = tid + it * 256;
        int r = c >> 3, k16 = (c & 7) * 16;
        *(uint4*)(sm + AQH + r * 144 + k16) = *(const uint4*)((const char*)(g_qh + qoff + (size_t)r * 64) + k16);
        *(uint4*)(sm + AQL + r * 144 + k16) = *(const uint4*)((const char*)(g_ql + qoff + (size_t)r * 64) + k16);
    }

    float Oc[8][4];
    #pragma unroll
    for (int dt = 0; dt < 8; dt++)
        #pragma unroll
        for (int e = 0; e < 4; e++) Oc[dt][e] = 0.0f;
    float m0 = -1e30f, m1 = -1e30f, l0 = 0.0f, l1 = 0.0f;
    int r0 = wid * 16 + g, r1 = r0 + 8;
    uint32_t qrow = (uint32_t)((wid * 16 + lr) * 144 + lh * 16);

    for (int ch = 0; ch < 3; ch++) {
        int kw = w - 1 + ch;
        if (kw < 0 || kw >= NWIN) continue;
        size_t koff = ((size_t)bh * SEQ + (size_t)kw * 128) * 64;

        __syncthreads();
        #pragma unroll
        for (int it = 0; it < 4; it++) {
            int c = tid + it * 256;
            int r = c >> 3, k16 = (c & 7) * 16;
            *(uint4*)(sm + AKH + r * 144 + k16) = *(const uint4*)((const char*)(g_kh + koff + (size_t)r * 64) + k16);
            *(uint4*)(sm + AKL + r * 144 + k16) = *(const uint4*)((const char*)(g_kl + koff + (size_t)r * 64) + k16);
        }
        #pragma unroll
        for (int it = 0; it < 4; it++) {
            int t = tid + it * 256;
            int d4 = t & 15, j2 = t >> 4;        // j2: 0..63
            float4 va = *(const float4*)(g_v + koff + (size_t)(2 * j2) * 64 + d4 * 4);
            float4 vb = *(const float4*)(g_v + koff + (size_t)(2 * j2 + 1) * 64 + d4 * 4);
            float a[4] = {va.x, va.y, va.z, va.w}, bb[4] = {vb.x, vb.y, vb.z, vb.w};
            #pragma unroll
            for (int dd = 0; dd < 4; dd++) {
                int d = d4 * 4 + dd;
                float ha = __bfloat162float(__float2bfloat16(a[dd]));
                float hb = __bfloat162float(__float2bfloat16(bb[dd]));
                *(uint32_t*)(sm + AVH + d * 272 + j2 * 4) = pack_bf(a[dd], bb[dd]);
                *(uint32_t*)(sm + AVL + d * 272 + j2 * 4) = pack_bf(a[dd] - ha, bb[dd] - hb);
            }
        }
        __syncthreads();

        // S = Q'K'^T (split 3 products)
        float Sc[16][4];
        #pragma unroll
        for (int nt = 0; nt < 16; nt++)
            #pragma unroll
            for (int e = 0; e < 4; e++) Sc[nt][e] = 0.0f;

        #pragma unroll
        for (int kd = 0; kd < 4; kd++) {
            uint32_t ah[4], al[4];
            LDMX4(ah[0], ah[1], ah[2], ah[3], smb + AQH + qrow + kd * 32);
            LDMX4(al[0], al[1], al[2], al[3], smb + AQL + qrow + kd * 32);
            #pragma unroll
            for (int bp = 0; bp < 8; bp++) {
                uint32_t krow = (uint32_t)((bp * 16 + lr) * 144 + kd * 32 + lh * 16);
                uint32_t t0, t1, t2, t3, u0, u1, u2, u3;
                LDMX4(t0, t1, t2, t3, smb + AKH + krow);
                hmma16816(Sc[2*bp],   ah[0], ah[1], ah[2], ah[3], t0, t2);
                hmma16816(Sc[2*bp],   al[0], al[1], al[2], al[3], t0, t2);
                hmma16816(Sc[2*bp+1], ah[0], ah[1], ah[2], ah[3], t1, t3);
                hmma16816(Sc[2*bp+1], al[0], al[1], al[2], al[3], t1, t3);
                LDMX4(u0, u1, u2, u3, smb + AKL + krow);
                hmma16816(Sc[2*bp],   ah[0], ah[1], ah[2], ah[3], u0, u2);
                hmma16816(Sc[2*bp+1], ah[0], ah[1], ah[2], ah[3], u1, u3);
            }
        }

        if (ch == 0) {
            #pragma unroll
            for (int nt = 0; nt < 16; nt++) {
                int c0 = nt * 8 + tg * 2;
                if (c0 < r0)     Sc[nt][0] = -1e30f;
                if (c0 + 1 < r0) Sc[nt][1] = -1e30f;
                if (c0 < r1)     Sc[nt][2] = -1e30f;
                if (c0 + 1 < r1) Sc[nt][3] = -1e30f;
            }
        } else if (ch == 2) {
            #pragma unroll
            for (int nt = 0; nt < 16; nt++) {
                int c0 = nt * 8 + tg * 2;
                if (c0 > r0)     Sc[nt][0] = -1e30f;
                if (c0 + 1 > r0) Sc[nt][1] = -1e30f;
                if (c0 > r1)     Sc[nt][2] = -1e30f;
                if (c0 + 1 > r1) Sc[nt][3] = -1e30f;
            }
        }

        float rm0 = -1e30f, rm1 = -1e30f;
        #pragma unroll
        for (int nt = 0; nt < 16; nt++) {
            rm0 = fmaxf(rm0, fmaxf(Sc[nt][0], Sc[nt][1]));
            rm1 = fmaxf(rm1, fmaxf(Sc[nt][2], Sc[nt][3]));
        }
        rm0 = fmaxf(rm0, __shfl_xor_sync(0xffffffffu, rm0, 1));
        rm0 = fmaxf(rm0, __shfl_xor_sync(0xffffffffu, rm0, 2));
        rm1 = fmaxf(rm1, __shfl_xor_sync(0xffffffffu, rm1, 1));
        rm1 = fmaxf(rm1, __shfl_xor_sync(0xffffffffu, rm1, 2));
        float mn0 = fmaxf(m0, rm0), mn1 = fmaxf(m1, rm1);
        float a0 = fexp(m0 - mn0), a1 = fexp(m1 - mn1);
        float rs0 = 0.0f, rs1 = 0.0f;
        #pragma unroll
        for (int nt = 0; nt < 16; nt++) {
            Sc[nt][0] = fexp(Sc[nt][0] - mn0);
            Sc[nt][1] = fexp(Sc[nt][1] - mn0);
            Sc[nt][2] = fexp(Sc[nt][2] - mn1);
            Sc[nt][3] = fexp(Sc[nt][3] - mn1);
            rs0 += Sc[nt][0] + Sc[nt][1];
            rs1 += Sc[nt][2] + Sc[nt][3];
        }
        rs0 += __shfl_xor_sync(0xffffffffu, rs0, 1);
        rs0 += __shfl_xor_sync(0xffffffffu, rs0, 2);
        rs1 += __shfl_xor_sync(0xffffffffu, rs1, 1);
        rs1 += __shfl_xor_sync(0xffffffffu, rs1, 2);
        l0 = l0 * a0 + rs0; l1 = l1 * a1 + rs1;
        m0 = mn0; m1 = mn1;
        #pragma unroll
        for (int dt = 0; dt < 8; dt++) {
            Oc[dt][0] *= a0; Oc[dt][1] *= a0;
            Oc[dt][2] *= a1; Oc[dt][3] *= a1;
        }

        // O += P'V' (P from fragments, split 3 products)
        #pragma unroll
        for (int jt = 0; jt < 8; jt++) {
            uint32_t ph[4], pl[4];
            float* s0 = Sc[2*jt];
            float* s1 = Sc[2*jt+1];
            float h00 = __bfloat162float(__float2bfloat16(s0[0]));
            float h01 = __bfloat162float(__float2bfloat16(s0[1]));
            float h02 = __bfloat162float(__float2bfloat16(s0[2]));
            float h03 = __bfloat162float(__float2bfloat16(s0[3]));
            float h10 = __bfloat162float(__float2bfloat16(s1[0]));
            float h11 = __bfloat162float(__float2bfloat16(s1[1]));
            float h12 = __bfloat162float(__float2bfloat16(s1[2]));
            float h13 = __bfloat162float(__float2bfloat16(s1[3]));
            ph[0] = pack_bf(s0[0], s0[1]); ph[1] = pack_bf(s0[2], s0[3]);
            ph[2] = pack_bf(s1[0], s1[1]); ph[3] = pack_bf(s1[2], s1[3]);
            pl[0] = pack_bf(s0[0]-h00, s0[1]-h01); pl[1] = pack_bf(s0[2]-h02, s0[3]-h03);
            pl[2] = pack_bf(s1[0]-h10, s1[1]-h11); pl[3] = pack_bf(s1[2]-h12, s1[3]-h13);
            #pragma unroll
            for (int dt = 0; dt < 4; dt++) {
                uint32_t vrow = (uint32_t)((dt * 16 + lr) * 272 + jt * 32 + lh * 16);
                uint32_t t0, t1, t2, t3, u0, u1, u2, u3;
                LDMX4(t0, t1, t2, t3, smb + AVH + vrow);
                hmma16816(Oc[2*dt],   ph[0], ph[1], ph[2], ph[3], t0, t2);
                hmma16816(Oc[2*dt],   pl[0], pl[1], pl[2], pl[3], t0, t2);
                hmma16816(Oc[2*dt+1], ph[0], ph[1], ph[2], ph[3], t1, t3);
                hmma16816(Oc[2*dt+1], pl[0], pl[1], pl[2], pl[3], t1, t3);
                LDMX4(u0, u1, u2, u3, smb + AVL + vrow);
                hmma16816(Oc[2*dt],   ph[0], ph[1], ph[2], ph[3], u0, u2);
                hmma16816(Oc[2*dt+1], ph[0], ph[1], ph[2], ph[3], u1, u3);
            }
        }
    }

    // epilogue: write split A' (hi, lo, hi) directly into g_a
    float i0 = 1.0f / l0, i1 = 1.0f / l1;
    int b = bh >> 4, h = bh & 15;
    size_t mr0 = (size_t)(b * SEQ + w * 128 + r0) * KTOT;
    size_t mr1 = (size_t)(b * SEQ + w * 128 + r1) * KTOT;
    #pragma unroll
    for (int dt = 0; dt < 8; dt++) {
        int k = h * 64 + dt * 8 + tg * 2;
        float o0 = Oc[dt][0] * i0, o1 = Oc[dt][1] * i0;
        float o2 = Oc[dt][2] * i1, o3 = Oc[dt][3] * i1;
        float h0 = __bfloat162float(__float2bfloat16(o0));
        float h1 = __bfloat162float(__float2bfloat16(o1));
        float h2 = __bfloat162float(__float2bfloat16(o2));
        float h3 = __bfloat162float(__float2bfloat16(o3));
        uint32_t hi0 = pack_bf(o0, o1), lo0 = pack_bf(o0 - h0, o1 - h1);
        uint32_t hi1 = pack_bf(o2, o3), lo1 = pack_bf(o2 - h2, o3 - h3);
        *(uint32_t*)(g_a + mr0 + k)        = hi0;
        *(uint32_t*)(g_a + mr0 + 1024 + k) = lo0;
        *(uint32_t*)(g_a + mr0 + 2048 + k) = hi0;
        *(uint32_t*)(g_a + mr1 + k)        = hi1;
        *(uint32_t*)(g_a + mr1 + 1024 + k) = lo1;
        *(uint32_t*)(g_a + mr1 + 2048 + k) = hi1;
    }
}

// ---------------- launch ----------------
extern "C" void kernel_launch(void* const* d_in, const int* in_sizes, int n_in,
                              void* d_out, int out_size) {
    const float* x       = (const float*)d_in[0];
    const float* w_qkv   = (const float*)d_in[1];
    const float* w_out   = (const float*)d_in[2];
    const float* q_scale = (const float*)d_in[3];
    const float* k_scale = (const float*)d_in[4];
    float* out = (float*)d_out;

    void *p_qkv, *p_a, *p_b1, *p_b2;
    cudaGetSymbolAddress(&p_qkv, g_qkv);
    cudaGetSymbolAddress(&p_a, g_a);
    cudaGetSymbolAddress(&p_b1, g_b1);
    cudaGetSymbolAddress(&p_b2, g_b2);

    cudaFuncSetAttribute(local_attn_kernel,
                         cudaFuncAttributeMaxDynamicSharedMemorySize, ATTN_SMEM);
    cudaFuncSetAttribute(gemm3x_kernel,
                         cudaFuncAttributeMaxDynamicSharedMemorySize, GEMM_SMEM);

    rope_table_kernel<<<(TBLROWS * 32 + 255) / 256, 256>>>();

    convert_a3_kernel<<<(NTOK * 1024) / 256, 256>>>(x, (__nv_bfloat16*)p_a);
    convert_b3_kernel<<<dim3(3072 / 32, 1024 / 32), dim3(32, 32)>>>(
        w_qkv, (__nv_bfloat16*)p_b1, 3072);
    convert_b3_kernel<<<dim3(1024 / 32, 1024 / 32), dim3(32, 32)>>>(
        w_out, (__nv_bfloat16*)p_b2, 1024);

    gemm3x_kernel<<<dim3(3072 / 128, NTOK / 128), 256, GEMM_SMEM>>>(
        (const __nv_bfloat16*)p_a, (const __nv_bfloat16*)p_b1, (float*)p_qkv, 3072);

    norm_rope_split_kernel<<<(NTOK * NHEADS) / 8, dim3(32, 8)>>>(
        (const float*)p_qkv, q_scale, k_scale);

    local_attn_kernel<<<dim3(NWIN, BHTOT), 256, ATTN_SMEM>>>();

    gemm3x_kernel<<<dim3(1024 / 128, NTOK / 128), 256, GEMM_SMEM>>>(
        (const __nv_bfloat16*)p_a, (const __nv_bfloat16*)p_b2, out, 1024);
}